// round 15
// baseline (speedup 1.0000x reference)
#include <cuda_runtime.h>
#include <math.h>

#define Bx 4
#define Nn 2048
#define Mm 2048
#define Pp 2048
#define NSs 1024
#define NA (Bx*Nn)    // 8192
#define NB (Bx*Mm)    // 8192
#define NSA (Bx*NSs)  // 4096
#define NC (Bx*Pp)    // 8192

typedef unsigned long long ull;

// Partial minima (atomic-free; every slot written exactly once per launch).
__device__ float g_rA[32 * NA];     // main rows:  [rc<32][q<8192]  (pc1_0 side)
__device__ float g_cA[8 * NB];      // main cols:  [qb<8][r<8192]   (pc2 side)
__device__ float g_rS[32 * NSA];    // seed rows:  [rc<32][q<4096]  (pc1_1 side)
__device__ float g_cS[4 * NB];      // seed cols:  [qb<4][r<8192]   (pc2 side)
__device__ float g_rC[8 * NC];      // conf rows:  [rc<8][b*2048+q]
__device__ float g_bsum[160];       // reduce1 partials (144 used)
__device__ float g_scalarC;

__device__ __forceinline__ ull pack2(float lo, float hi) {
    ull r;
    asm("mov.b64 %0, {%1, %2};" : "=l"(r) : "f"(lo), "f"(hi));
    return r;
}
__device__ __forceinline__ void unpack2(ull v, float& lo, float& hi) {
    asm("mov.b64 {%0, %1}, %2;" : "=f"(lo), "=f"(hi) : "l"(v));
}
__device__ __forceinline__ ull ffma2(ull a, ull b, ull c) {
    ull d;
    asm("fma.rn.f32x2 %0, %1, %2, %3;" : "=l"(d) : "l"(a), "l"(b), "l"(c));
    return d;
}
__device__ __forceinline__ ull add2(ull a, ull b) {
    ull d;
    asm("add.rn.f32x2 %0, %1, %2;" : "=l"(d) : "l"(a), "l"(b));
    return d;
}

// Bidirectional NN: 448 uniform blocks, 256 threads, each block = 1024 queries
// (4/thread, 2 f32x2 packs) x 256 refs. Each pair evaluated ONCE; row mins in
// registers (thread-exclusive), col mins in warp-owned smem rows with rotated
// lane indexing (race-free by warp instruction ordering).
//   [0,256):   MAIN qb=bi>>5 (8), rc=bi&31 (32): pc1_0 x pc2 -> g_rA, g_cA
//   [256,384): SEED qb=bi>>5 (4), rc=bi&31:      pc1_1 x pc2 -> g_rS, g_cS
//   [384,448): CONF b=bi>>4, qb=(bi&15)>>3, rc=bi&7: pc3[b] x pc2[b] -> g_rC (rows only)
__global__ void __launch_bounds__(256) nn_bidir(
    const float* __restrict__ pc1_0, const float* __restrict__ pc1_1,
    const float* __restrict__ pc2,   const float* __restrict__ pc3)
{
    __shared__ ulonglong2 sRa[256];   // (xx2 = (-2x,-2x), yy2)
    __shared__ ulonglong2 sRb[256];   // (zz2, ww2 = (|r|^2,|r|^2))
    __shared__ float scol[8 * 256];   // per-warp col partials

    const float* Q; const float* R; float* rowOut; float* colOut;
    bool doCol;
    int bi = blockIdx.x;
    if (bi < 256) {
        int qb = bi >> 5, rc = bi & 31;
        Q = pc1_0 + qb * 1024 * 3;
        R = pc2   + rc * 256 * 3;
        rowOut = g_rA + rc * NA + qb * 1024;
        colOut = g_cA + qb * NB + rc * 256;
        doCol = true;
    } else if (bi < 384) {
        bi -= 256;
        int qb = bi >> 5, rc = bi & 31;
        Q = pc1_1 + qb * 1024 * 3;
        R = pc2   + rc * 256 * 3;
        rowOut = g_rS + rc * NSA + qb * 1024;
        colOut = g_cS + qb * NB + rc * 256;
        doCol = true;
    } else {
        bi -= 384;
        int b = bi >> 4, rem = bi & 15;
        int qb = rem >> 3, rc = rem & 7;
        Q = pc3 + b * Pp * 3 + qb * 1024 * 3;
        R = pc2 + b * Mm * 3 + rc * 256 * 3;
        rowOut = g_rC + rc * NC + b * 2048 + qb * 1024;
        colOut = nullptr;
        doCol = false;
    }

    int tid = threadIdx.x;

    // Stage 256 refs (1/thread), duplicated into both f32x2 halves.
    {
        float rx = R[tid * 3 + 0];
        float ry = R[tid * 3 + 1];
        float rz = R[tid * 3 + 2];
        float w  = rx * rx + ry * ry + rz * rz;
        ulonglong2 a, bb;
        a.x  = pack2(-2.0f * rx, -2.0f * rx);
        a.y  = pack2(-2.0f * ry, -2.0f * ry);
        bb.x = pack2(-2.0f * rz, -2.0f * rz);
        bb.y = pack2(w, w);
        sRa[tid] = a;
        sRb[tid] = bb;
    }
    // Init warp col partials (8*256/256 = 8 per thread).
    #pragma unroll
    for (int i = 0; i < 8; i++) scol[i * 256 + tid] = 3.0e38f;

    // 4 queries/thread, coalesced stride-256.
    float qx[4], qy[4], qz[4], qq[4];
    #pragma unroll
    for (int i = 0; i < 4; i++) {
        int q = i * 256 + tid;
        qx[i] = Q[q * 3 + 0];
        qy[i] = Q[q * 3 + 1];
        qz[i] = Q[q * 3 + 2];
        qq[i] = qx[i] * qx[i] + qy[i] * qy[i] + qz[i] * qz[i];
    }
    ull px0 = pack2(qx[0], qx[1]), py0 = pack2(qy[0], qy[1]), pz0 = pack2(qz[0], qz[1]);
    ull px1 = pack2(qx[2], qx[3]), py1 = pack2(qy[2], qy[3]), pz1 = pack2(qz[2], qz[3]);
    ull qqp0 = pack2(qq[0], qq[1]), qqp1 = pack2(qq[2], qq[3]);

    __syncthreads();

    float mn[4];
    #pragma unroll
    for (int i = 0; i < 4; i++) mn[i] = 3.0e38f;

    int wbase = (tid >> 5) * 256;   // warp-owned scol row

    if (doCol) {
        // Full d2 = qq + w - 2 q.r in-chain (col mins need qq per query).
        #pragma unroll 4
        for (int j = 0; j < 256; j++) {
            int jj = (tid + j) & 255;
            ulonglong2 ra = sRa[jj];
            ulonglong2 rb = sRb[jj];
            ull base0 = add2(rb.y, qqp0);
            ull base1 = add2(rb.y, qqp1);
            ull t0 = ffma2(px0, ra.x, ffma2(py0, ra.y, ffma2(pz0, rb.x, base0)));
            ull t1 = ffma2(px1, ra.x, ffma2(py1, ra.y, ffma2(pz1, rb.x, base1)));
            float d0, d1, d2, d3;
            unpack2(t0, d0, d1);
            unpack2(t1, d2, d3);
            mn[0] = fminf(mn[0], d0);
            mn[1] = fminf(mn[1], d1);
            mn[2] = fminf(mn[2], d2);
            mn[3] = fminf(mn[3], d3);
            float h = fminf(fminf(d0, d1), fminf(d2, d3));
            int ci = wbase + jj;
            scol[ci] = fminf(scol[ci], h);
        }
        #pragma unroll
        for (int i = 0; i < 4; i++)
            rowOut[i * 256 + tid] = fmaxf(mn[i], 0.0f);

        __syncthreads();
        // Merge 8 warp partials per ref column.
        float c = scol[tid];
        #pragma unroll
        for (int w = 1; w < 8; w++) c = fminf(c, scol[w * 256 + tid]);
        colOut[tid] = fmaxf(c, 0.0f);
    } else {
        // Rows only: d' = w - 2 q.r, qq shifted after the min.
        #pragma unroll 4
        for (int j = 0; j < 256; j++) {
            int jj = (tid + j) & 255;
            ulonglong2 ra = sRa[jj];
            ulonglong2 rb = sRb[jj];
            ull t0 = ffma2(px0, ra.x, ffma2(py0, ra.y, ffma2(pz0, rb.x, rb.y)));
            ull t1 = ffma2(px1, ra.x, ffma2(py1, ra.y, ffma2(pz1, rb.x, rb.y)));
            float d0, d1, d2, d3;
            unpack2(t0, d0, d1);
            unpack2(t1, d2, d3);
            mn[0] = fminf(mn[0], d0);
            mn[1] = fminf(mn[1], d1);
            mn[2] = fminf(mn[2], d2);
            mn[3] = fminf(mn[3], d3);
        }
        #pragma unroll
        for (int i = 0; i < 4; i++)
            rowOut[i * 256 + tid] = fmaxf(mn[i] + qq[i], 0.0f);
    }
}

// reduce1: 144 blocks x 256 threads, 1 thread per query/ref (36864 total).
__global__ void __launch_bounds__(256) reduce1_kernel(const float* __restrict__ pc1_3) {
    int i = blockIdx.x * 256 + threadIdx.x;
    float val;
    if (i < 8192) {                       // main rows (pc1_0 NN in pc2)
        float m = 3.0e38f;
        #pragma unroll
        for (int k = 0; k < 32; k++) m = fminf(m, g_rA[k * NA + i]);
        val = (0.5f / (float)NA) * sqrtf(m);
    } else if (i < 16384) {               // main cols (pc2 NN in pc1_0)
        int r = i - 8192;
        float m = 3.0e38f;
        #pragma unroll
        for (int k = 0; k < 8; k++) m = fminf(m, g_cA[k * NB + r]);
        val = (0.5f / (float)NB) * sqrtf(m);
    } else if (i < 20480) {               // seed rows (pc1_1 NN in pc2)
        int q = i - 16384;
        float m = 3.0e38f;
        #pragma unroll
        for (int k = 0; k < 32; k++) m = fminf(m, g_rS[k * NSA + q]);
        val = (1.0f / (float)NSA) * sqrtf(m);
    } else if (i < 28672) {               // seed cols (pc2 NN in pc1_1)
        int r = i - 20480;
        float m = 3.0e38f;
        #pragma unroll
        for (int k = 0; k < 4; k++) m = fminf(m, g_cS[k * NB + r]);
        val = (1.0f / (float)NB) * sqrtf(m);
    } else {                              // confidence
        int qi = i - 28672;               // 0..8191 = b*2048+q
        float m = 3.0e38f;
        #pragma unroll
        for (int k = 0; k < 8; k++) m = fminf(m, g_rC[k * NC + qi]);
        float df = pc1_3[qi] - expf(-sqrtf(m));
        val = (1.0f / (float)NC) * df * df;
    }

    __shared__ float sh[256];
    int t = threadIdx.x;
    sh[t] = val;
    __syncthreads();
    for (int s = 128; s > 0; s >>= 1) {
        if (t < s) sh[t] += sh[t + s];
        __syncthreads();
    }
    if (t == 0) g_bsum[blockIdx.x] = sh[0];
}

// reduce2: fold 144 block partials deterministically.
__global__ void __launch_bounds__(256) reduce2_kernel() {
    __shared__ float sh[256];
    int t = threadIdx.x;
    sh[t] = (t < 144) ? g_bsum[t] : 0.0f;
    __syncthreads();
    for (int s = 128; s > 0; s >>= 1) {
        if (t < s) sh[t] += sh[t + s];
        __syncthreads();
    }
    if (t == 0) g_scalarC = sh[0];
}

// out[b,n,m] = C + 0.5*dist(pc1_0[b,n], pc2[b,m])
// Block tile: 64 rows x 128 cols, 256 threads; each thread 8 rows x 4 cols.
__global__ void __launch_bounds__(256) emd_kernel(
    const float* __restrict__ pc1_0, const float* __restrict__ pc2,
    float* __restrict__ out)
{
    __shared__ float4 sP[128];  // (-2x,-2y,-2z,|r|^2) per col
    __shared__ float4 sQ[64];   // (qx,qy,qz,qq) per row
    int b = blockIdx.z;
    const float* Qb = pc1_0 + (size_t)b * Nn * 3;
    const float* Rb = pc2   + (size_t)b * Mm * 3;
    int tid = threadIdx.x;

    if (tid < 128) {
        int m = blockIdx.x * 128 + tid;
        float rx = Rb[m * 3 + 0];
        float ry = Rb[m * 3 + 1];
        float rz = Rb[m * 3 + 2];
        sP[tid] = make_float4(-2.0f * rx, -2.0f * ry, -2.0f * rz,
                              rx * rx + ry * ry + rz * rz);
    } else if (tid < 192) {
        int r = tid - 128;
        int row = blockIdx.y * 64 + r;
        float qx = Qb[row * 3 + 0];
        float qy = Qb[row * 3 + 1];
        float qz = Qb[row * 3 + 2];
        sQ[r] = make_float4(qx, qy, qz, qx * qx + qy * qy + qz * qz);
    }
    __syncthreads();

    float C = g_scalarC;
    int warp = tid >> 5;
    int lane = tid & 31;
    int ml = lane * 4;

    float4 a  = sP[ml + 0];
    float4 bb = sP[ml + 1];
    float4 c  = sP[ml + 2];
    float4 e  = sP[ml + 3];

    size_t rowBase = ((size_t)(b * Nn) + blockIdx.y * 64 + warp * 8) * Mm
                     + blockIdx.x * 128 + ml;

    #pragma unroll 8
    for (int r = 0; r < 8; r++) {
        float4 qv = sQ[warp * 8 + r];  // warp-uniform broadcast
        float d0 = qv.w + fmaf(qv.x, a.x,  fmaf(qv.y, a.y,  fmaf(qv.z, a.z,  a.w)));
        float d1 = qv.w + fmaf(qv.x, bb.x, fmaf(qv.y, bb.y, fmaf(qv.z, bb.z, bb.w)));
        float d2 = qv.w + fmaf(qv.x, c.x,  fmaf(qv.y, c.y,  fmaf(qv.z, c.z,  c.w)));
        float d3 = qv.w + fmaf(qv.x, e.x,  fmaf(qv.y, e.y,  fmaf(qv.z, e.z,  e.w)));
        d0 = fmaxf(d0, 1e-30f);
        d1 = fmaxf(d1, 1e-30f);
        d2 = fmaxf(d2, 1e-30f);
        d3 = fmaxf(d3, 1e-30f);
        float4 o;
        o.x = fmaf(0.5f, d0 * rsqrtf(d0), C);
        o.y = fmaf(0.5f, d1 * rsqrtf(d1), C);
        o.z = fmaf(0.5f, d2 * rsqrtf(d2), C);
        o.w = fmaf(0.5f, d3 * rsqrtf(d3), C);
        *reinterpret_cast<float4*>(&out[rowBase + (size_t)r * Mm]) = o;
    }
}

extern "C" void kernel_launch(void* const* d_in, const int* in_sizes, int n_in,
                              void* d_out, int out_size) {
    const float* pc1_0 = (const float*)d_in[0];  // [4,2048,3]
    const float* pc1_1 = (const float*)d_in[1];  // [4,1024,3]
    const float* pc1_3 = (const float*)d_in[2];  // [4,2048,1]
    const float* pc2   = (const float*)d_in[3];  // [4,2048,3]
    const float* pc3   = (const float*)d_in[4];  // [4,2048,3]
    float* out = (float*)d_out;                  // [4,2048,2048]

    nn_bidir<<<448, 256>>>(pc1_0, pc1_1, pc2, pc3);
    reduce1_kernel<<<144, 256>>>(pc1_3);
    reduce2_kernel<<<1, 256>>>();
    emd_kernel<<<dim3(Mm / 128, Nn / 64, Bx), 256>>>(pc1_0, pc2, out);
}